// round 2
// baseline (speedup 1.0000x reference)
#include <cuda_runtime.h>
#include <stdint.h>

#define N_FEATURES 4096
#define N_GROUPS   1024

// Scratch: folded coefficient vector v[f] = sum over indices hitting f of
// w_flat[i] * diag_w[seg_ids[i]] * dense_W[seg_ids[i]].
__device__ float g_v[N_FEATURES];

// ---------------------------------------------------------------------------
// Kernel 1: build the folded coefficient vector (single block, trivial cost).
// Detects int32 vs int64 index dtype at runtime: if the data is int64
// (little-endian), every odd 32-bit word is a high half == 0 (all indices
// < 4096). 16 consecutive random-in-[0,4096) int32 values being zero is
// impossible, so the check is unambiguous.
// ---------------------------------------------------------------------------
__global__ void build_coef_kernel(const void* __restrict__ flat_idx_raw,
                                  const void* __restrict__ seg_ids_raw,
                                  const float* __restrict__ w_flat,
                                  const float* __restrict__ diag_w,
                                  const float* __restrict__ dense_W,
                                  int total) {
    __shared__ float sv[N_FEATURES];
    __shared__ int s_is64;
    int tid = threadIdx.x;

    for (int i = tid; i < N_FEATURES; i += blockDim.x) sv[i] = 0.0f;

    if (tid == 0) {
        const int* w = (const int*)flat_idx_raw;
        int all0 = 1;
        #pragma unroll
        for (int k = 0; k < 16; k++) {
            if (w[2 * k + 1] != 0) { all0 = 0; break; }
        }
        s_is64 = all0;
    }
    __syncthreads();

    const int is64 = s_is64;
    const int*       fi32 = (const int*)flat_idx_raw;
    const long long* fi64 = (const long long*)flat_idx_raw;
    const int*       sg32 = (const int*)seg_ids_raw;
    const long long* sg64 = (const long long*)seg_ids_raw;

    for (int i = tid; i < total; i += blockDim.x) {
        int f = is64 ? (int)fi64[i] : fi32[i];
        int g = is64 ? (int)sg64[i] : sg32[i];
        float c = w_flat[i] * diag_w[g] * dense_W[g];
        atomicAdd(&sv[f], c);
    }
    __syncthreads();

    for (int i = tid; i < N_FEATURES; i += blockDim.x) g_v[i] = sv[i];
}

// ---------------------------------------------------------------------------
// Kernel 2: GEMV  out[b] = dot(x[b, :], v).  One warp per row.
// Row = 4096 floats = 1024 float4; each lane does 32 independent float4
// loads (fully coalesced, 128B per warp transaction) -> HBM-bound stream.
// v is 16 KB and L2-resident after the first wave.
// ---------------------------------------------------------------------------
__global__ void __launch_bounds__(256) gemv_kernel(const float4* __restrict__ x,
                                                   float* __restrict__ out,
                                                   int batch) {
    const int warps_per_block = blockDim.x >> 5;
    int row = blockIdx.x * warps_per_block + (threadIdx.x >> 5);
    int lane = threadIdx.x & 31;
    if (row >= batch) return;

    const float4* __restrict__ xr = x + (size_t)row * (N_FEATURES / 4);
    const float4* __restrict__ vv = (const float4*)g_v;

    float acc = 0.0f;
    #pragma unroll 8
    for (int j = 0; j < (N_FEATURES / 4) / 32; j++) {
        int col = j * 32 + lane;
        float4 xv = __ldg(&xr[col]);
        float4 cv = __ldg(&vv[col]);
        acc += xv.x * cv.x + xv.y * cv.y + xv.z * cv.z + xv.w * cv.w;
    }

    #pragma unroll
    for (int o = 16; o; o >>= 1) acc += __shfl_xor_sync(0xffffffffu, acc, o);

    if (lane == 0) out[row] = acc;
}

// ---------------------------------------------------------------------------
// Inputs (metadata order): x [B*4096] f32, flat_idx [total], seg_ids [total],
// w_flat [total] f32, diag_w [1024] f32, dense_W [1024] f32. Output: [B] f32.
// ---------------------------------------------------------------------------
extern "C" void kernel_launch(void* const* d_in, const int* in_sizes, int n_in,
                              void* d_out, int out_size) {
    const float* x       = (const float*)d_in[0];
    const void*  flatidx = d_in[1];
    const void*  segids  = d_in[2];
    const float* w_flat  = (const float*)d_in[3];
    const float* diag_w  = (const float*)d_in[4];
    const float* dense_W = (const float*)d_in[5];

    int total = in_sizes[1];
    int batch = in_sizes[0] / N_FEATURES;

    build_coef_kernel<<<1, 256>>>(flatidx, segids, w_flat, diag_w, dense_W, total);

    int warps_per_block = 8;  // 256 threads
    int blocks = (batch + warps_per_block - 1) / warps_per_block;
    gemv_kernel<<<blocks, 256>>>((const float4*)x, (float*)d_out, batch);
}

// round 3
// speedup vs baseline: 1.0449x; 1.0449x over previous
#include <cuda_runtime.h>
#include <cuda_pipeline_primitives.h>
#include <stdint.h>

#define NF            4096
#define ROWS_PER_BLK  8
#define TILE          512            // floats per row-tile
#define NT            (NF / TILE)    // 8 tiles
#define THREADS       256

// Fused kernel:
//  Phase A (per block): build folded coefficient vector
//      v[f] = sum_i [flat_idx[i]==f] * w_flat[i] * diag_w[seg_ids[i]] * dense_W[seg_ids[i]]
//  into shared memory (tiny: ~5115 elements, L2-hot after first wave), while the
//  first two x-tiles are already in flight via cp.async.
//  Phase B: out[row] = dot(x[row,:], v) for 8 rows/block, streaming x through
//  double-buffered shared tiles with cp.async (bytes-in-flight decoupled from
//  register pressure -> HBM-saturating).
__global__ void __launch_bounds__(THREADS)
fused_group_gemv(const float* __restrict__ x,
                 const void* __restrict__ flat_idx_raw,
                 const void* __restrict__ seg_ids_raw,
                 const float* __restrict__ w_flat,
                 const float* __restrict__ diag_w,
                 const float* __restrict__ dense_W,
                 int total, int batch,
                 float* __restrict__ out) {
    __shared__ __align__(16) float sv[NF];                       // 16 KB
    __shared__ __align__(16) float sx[2][ROWS_PER_BLK][TILE];    // 32 KB

    const int tid  = threadIdx.x;
    const int w    = tid >> 5;
    const int lane = tid & 31;
    const int row  = blockIdx.x * ROWS_PER_BLK + w;
    const bool valid = row < batch;

    // Row pointer (clamped so OOB warps stream a duplicate row harmlessly).
    const float* __restrict__ xrow =
        x + (size_t)(valid ? row : batch - 1) * NF;

    // ---- Issue prefetch of tiles 0 and 1 FIRST (overlaps the v-build) ----
    // Each thread copies exactly the float4 chunks it will later read:
    // row w, float4 indices lane + 32*j, j=0..3  (512 B contiguous per warp/j).
    #pragma unroll
    for (int s = 0; s < 2; s++) {
        #pragma unroll
        for (int j = 0; j < 4; j++) {
            const int c = (lane + 32 * j) * 4;
            __pipeline_memcpy_async(&sx[s][w][c], xrow + s * TILE + c, 16);
        }
        __pipeline_commit();
    }

    // ---- Phase A: build v in shared ----
    for (int i = tid; i < NF; i += THREADS) sv[i] = 0.0f;

    // int32 vs int64 index dtype detection (uniform across block):
    // for int64 little-endian, the 16 odd 32-bit words are all 0 (idx < 4096);
    // impossible for 16 random int32 indices.
    const int* probe = (const int*)flat_idx_raw;
    int is64 = 1;
    #pragma unroll
    for (int k = 0; k < 16; k++) is64 &= (probe[2 * k + 1] == 0);

    __syncthreads();  // sv zeroed before atomics

    const int*       fi32 = (const int*)flat_idx_raw;
    const long long* fi64 = (const long long*)flat_idx_raw;
    const int*       sg32 = (const int*)seg_ids_raw;
    const long long* sg64 = (const long long*)seg_ids_raw;

    #pragma unroll 4
    for (int i = tid; i < total; i += THREADS) {
        int f = is64 ? (int)fi64[i] : fi32[i];
        int g = is64 ? (int)sg64[i] : sg32[i];
        float c = w_flat[i] * diag_w[g] * dense_W[g];
        atomicAdd(&sv[f], c);
    }
    __syncthreads();  // sv complete before any tile compute

    // ---- Phase B: streamed dot product over 8 tiles, double buffered ----
    float acc = 0.0f;

    #pragma unroll
    for (int t = 0; t < NT; t++) {
        // Wait until tile t's copies (this thread's) have landed.
        if (t < NT - 1) __pipeline_wait_prior(1);
        else           __pipeline_wait_prior(0);

        const float4* __restrict__ xs = (const float4*)sx[t & 1][w];
        const float4* __restrict__ vs = (const float4*)(sv + t * TILE);

        float a0 = 0.f, a1 = 0.f, a2 = 0.f, a3 = 0.f;
        {
            float4 xa = xs[lane +  0], va = vs[lane +  0];
            float4 xb = xs[lane + 32], vb = vs[lane + 32];
            float4 xc = xs[lane + 64], vc = vs[lane + 64];
            float4 xd = xs[lane + 96], vd = vs[lane + 96];
            a0 = xa.x * va.x + xa.y * va.y + xa.z * va.z + xa.w * va.w;
            a1 = xb.x * vb.x + xb.y * vb.y + xb.z * vb.z + xb.w * vb.w;
            a2 = xc.x * vc.x + xc.y * vc.y + xc.z * vc.z + xc.w * vc.w;
            a3 = xd.x * vd.x + xd.y * vd.y + xd.z * vd.z + xd.w * vd.w;
        }
        acc += (a0 + a1) + (a2 + a3);

        // Prefetch tile t+2 into the buffer just consumed (thread-local WAR:
        // issued after this thread's reads of that buffer).
        if (t + 2 < NT) {
            #pragma unroll
            for (int j = 0; j < 4; j++) {
                const int c = (lane + 32 * j) * 4;
                __pipeline_memcpy_async(&sx[t & 1][w][c],
                                        xrow + (t + 2) * TILE + c, 16);
            }
            __pipeline_commit();
        }
    }

    // Warp reduction -> one output per row.
    #pragma unroll
    for (int o = 16; o; o >>= 1) acc += __shfl_xor_sync(0xffffffffu, acc, o);

    if (lane == 0 && valid) out[row] = acc;
}

// Inputs (metadata order): x [B*4096] f32, flat_idx [total], seg_ids [total],
// w_flat [total] f32, diag_w [1024] f32, dense_W [1024] f32. Output: [B] f32.
extern "C" void kernel_launch(void* const* d_in, const int* in_sizes, int n_in,
                              void* d_out, int out_size) {
    const float* x       = (const float*)d_in[0];
    const void*  flatidx = d_in[1];
    const void*  segids  = d_in[2];
    const float* w_flat  = (const float*)d_in[3];
    const float* diag_w  = (const float*)d_in[4];
    const float* dense_W = (const float*)d_in[5];

    int total = in_sizes[1];
    int batch = in_sizes[0] / NF;

    int blocks = (batch + ROWS_PER_BLK - 1) / ROWS_PER_BLK;
    fused_group_gemv<<<blocks, THREADS>>>(x, flatidx, segids, w_flat, diag_w,
                                          dense_W, total, batch,
                                          (float*)d_out);
}

// round 4
// speedup vs baseline: 1.3946x; 1.3346x over previous
#include <cuda_runtime.h>
#include <cuda_pipeline_primitives.h>
#include <stdint.h>

#define NF            4096
#define ROWS_PER_BLK  8
#define TILE          512            // floats per row per stage
#define NT            (NF / TILE)    // 8 tiles
#define THREADS       256

__device__ float g_v[NF];

// ---------------------------------------------------------------------------
// Kernel A: build folded coefficient vector
//   v[f] = sum_i [flat_idx[i]==f] * w_flat[i] * diag_w[seg_ids[i]] * dense_W[seg_ids[i]]
// Single block, 1024 threads -> ceil(5115/1024)=5 rounds of independent loads.
// int64-vs-int32 index dtype detected from the data (high words all zero).
// ---------------------------------------------------------------------------
__global__ void __launch_bounds__(1024)
build_coef_kernel(const void* __restrict__ flat_idx_raw,
                  const void* __restrict__ seg_ids_raw,
                  const float* __restrict__ w_flat,
                  const float* __restrict__ diag_w,
                  const float* __restrict__ dense_W,
                  int total) {
    __shared__ float sv[NF];
    const int tid = threadIdx.x;

    for (int i = tid; i < NF; i += 1024) sv[i] = 0.0f;

    const int* probe = (const int*)flat_idx_raw;
    int is64 = 1;
    #pragma unroll
    for (int k = 0; k < 16; k++) is64 &= (probe[2 * k + 1] == 0);

    __syncthreads();

    const int*       fi32 = (const int*)flat_idx_raw;
    const long long* fi64 = (const long long*)flat_idx_raw;
    const int*       sg32 = (const int*)seg_ids_raw;
    const long long* sg64 = (const long long*)seg_ids_raw;

    #pragma unroll 5
    for (int i = tid; i < total; i += 1024) {
        int f = is64 ? (int)fi64[i] : fi32[i];
        int g = is64 ? (int)sg64[i] : sg32[i];
        float c = w_flat[i] * diag_w[g] * dense_W[g];
        atomicAdd(&sv[f], c);
    }
    __syncthreads();

    for (int i = tid; i < NF; i += 1024) g_v[i] = sv[i];
}

// ---------------------------------------------------------------------------
// Kernel B: out[b] = dot(x[b,:], v).  One warp per row, 8 rows/block.
// v lives in shared (copied once from g_v; L2-hot).  x is streamed through
// double-buffered cp.async stages (16 KB/stage/block) so DRAM bytes-in-flight
// are decoupled from register pressure.  Prefetches issue before anything
// else so HBM ramps immediately.
// ---------------------------------------------------------------------------
__global__ void __launch_bounds__(THREADS)
gemv_kernel(const float* __restrict__ x,
            float* __restrict__ out,
            int batch) {
    __shared__ __align__(16) float sv[NF];                       // 16 KB
    __shared__ __align__(16) float sx[2][ROWS_PER_BLK][TILE];    // 32 KB

    const int tid  = threadIdx.x;
    const int w    = tid >> 5;
    const int lane = tid & 31;
    const int row  = blockIdx.x * ROWS_PER_BLK + w;
    const bool valid = row < batch;

    const float* __restrict__ xrow =
        x + (size_t)(valid ? row : batch - 1) * NF;

    // Prefetch tiles 0 and 1 first. Each thread copies exactly the chunks it
    // later reads (lane + 32*j float4s): consecutive lanes -> 512B coalesced.
    #pragma unroll
    for (int s = 0; s < 2; s++) {
        #pragma unroll
        for (int j = 0; j < 4; j++) {
            const int c = (lane + 32 * j) * 4;
            __pipeline_memcpy_async(&sx[s][w][c], xrow + s * TILE + c, 16);
        }
        __pipeline_commit();
    }

    // Copy v into shared while the first prefetches are in flight.
    {
        const float4* __restrict__ gv = (const float4*)g_v;
        float4*       __restrict__ svv = (float4*)sv;
        #pragma unroll
        for (int i = 0; i < (NF / 4) / THREADS; i++)
            svv[tid + i * THREADS] = gv[tid + i * THREADS];
    }
    __syncthreads();

    float acc = 0.0f;

    #pragma unroll
    for (int t = 0; t < NT; t++) {
        if (t < NT - 1) __pipeline_wait_prior(1);
        else            __pipeline_wait_prior(0);

        const float4* __restrict__ xs = (const float4*)sx[t & 1][w];
        const float4* __restrict__ vs = (const float4*)(sv + t * TILE);

        float4 xa = xs[lane +  0], va = vs[lane +  0];
        float4 xb = xs[lane + 32], vb = vs[lane + 32];
        float4 xc = xs[lane + 64], vc = vs[lane + 64];
        float4 xd = xs[lane + 96], vd = vs[lane + 96];

        float a0 = xa.x * va.x + xa.y * va.y + xa.z * va.z + xa.w * va.w;
        float a1 = xb.x * vb.x + xb.y * vb.y + xb.z * vb.z + xb.w * vb.w;
        float a2 = xc.x * vc.x + xc.y * vc.y + xc.z * vc.z + xc.w * vc.w;
        float a3 = xd.x * vd.x + xd.y * vd.y + xd.z * vd.z + xd.w * vd.w;
        acc += (a0 + a1) + (a2 + a3);

        // Refill the buffer just consumed with tile t+2 (thread-local WAR:
        // this thread's reads of the buffer are complete).
        if (t + 2 < NT) {
            #pragma unroll
            for (int j = 0; j < 4; j++) {
                const int c = (lane + 32 * j) * 4;
                __pipeline_memcpy_async(&sx[t & 1][w][c],
                                        xrow + (t + 2) * TILE + c, 16);
            }
            __pipeline_commit();
        }
    }

    #pragma unroll
    for (int o = 16; o; o >>= 1) acc += __shfl_xor_sync(0xffffffffu, acc, o);

    if (lane == 0 && valid) out[row] = acc;
}

// Inputs (metadata order): x [B*4096] f32, flat_idx [total], seg_ids [total],
// w_flat [total] f32, diag_w [1024] f32, dense_W [1024] f32. Output: [B] f32.
extern "C" void kernel_launch(void* const* d_in, const int* in_sizes, int n_in,
                              void* d_out, int out_size) {
    const float* x       = (const float*)d_in[0];
    const void*  flatidx = d_in[1];
    const void*  segids  = d_in[2];
    const float* w_flat  = (const float*)d_in[3];
    const float* diag_w  = (const float*)d_in[4];
    const float* dense_W = (const float*)d_in[5];

    int total = in_sizes[1];
    int batch = in_sizes[0] / NF;

    build_coef_kernel<<<1, 1024>>>(flatidx, segids, w_flat, diag_w, dense_W,
                                   total);

    int blocks = (batch + ROWS_PER_BLK - 1) / ROWS_PER_BLK;
    gemv_kernel<<<blocks, THREADS>>>(x, (float*)d_out, batch);
}

// round 5
// speedup vs baseline: 1.5468x; 1.1091x over previous
#include <cuda_runtime.h>
#include <cuda_pipeline_primitives.h>
#include <stdint.h>

#define NF            4096
#define ROWS_PER_BLK  8
#define TILE          512            // floats per row per stage
#define NT            (NF / TILE)    // 8 tiles
#define THREADS       256

__device__ float g_v[NF];

// ---------------------------------------------------------------------------
// Kernel A: build folded coefficient vector
//   v[f] = sum_i [flat_idx[i]==f] * w_flat[i] * diag_w[seg_ids[i]] * dense_W[seg_ids[i]]
// Triggers programmatic launch completion immediately so the dependent GEMV
// can start its x-prefetch while this runs.
// ---------------------------------------------------------------------------
__global__ void __launch_bounds__(1024)
build_coef_kernel(const void* __restrict__ flat_idx_raw,
                  const void* __restrict__ seg_ids_raw,
                  const float* __restrict__ w_flat,
                  const float* __restrict__ diag_w,
                  const float* __restrict__ dense_W,
                  int total) {
    cudaTriggerProgrammaticLaunchCompletion();

    __shared__ float sv[NF];
    __shared__ float gsc[1024];      // per-group diag_w * dense_W
    const int tid = threadIdx.x;

    for (int i = tid; i < NF; i += 1024) sv[i] = 0.0f;
    if (tid < 1024) {
        // independent loads; 1024 groups, one per thread
        gsc[tid] = diag_w[tid] * dense_W[tid];
    }

    const int* probe = (const int*)flat_idx_raw;
    int is64 = 1;
    #pragma unroll
    for (int k = 0; k < 16; k++) is64 &= (probe[2 * k + 1] == 0);

    __syncthreads();

    const int*       fi32 = (const int*)flat_idx_raw;
    const long long* fi64 = (const long long*)flat_idx_raw;
    const int*       sg32 = (const int*)seg_ids_raw;
    const long long* sg64 = (const long long*)seg_ids_raw;

    #pragma unroll 5
    for (int i = tid; i < total; i += 1024) {
        int f = is64 ? (int)fi64[i] : fi32[i];
        int g = is64 ? (int)sg64[i] : sg32[i];
        atomicAdd(&sv[f], w_flat[i] * gsc[g]);
    }
    __syncthreads();

    for (int i = tid; i < NF; i += 1024) g_v[i] = sv[i];
}

// ---------------------------------------------------------------------------
// Kernel B: out[b] = dot(x[b,:], v).  One warp per row, 8 rows/block.
// Launched with programmatic stream serialization: prefetches x before
// cudaGridDependencySynchronize(), then copies v to shared and streams.
// __launch_bounds__(256,4) forces 4 blocks/SM (smem-bound limit).
// ---------------------------------------------------------------------------
__global__ void __launch_bounds__(THREADS, 4)
gemv_kernel(const float* __restrict__ x,
            float* __restrict__ out,
            int batch) {
    __shared__ __align__(16) float sv[NF];                       // 16 KB
    __shared__ __align__(16) float sx[2][ROWS_PER_BLK][TILE];    // 32 KB

    const int tid  = threadIdx.x;
    const int w    = tid >> 5;
    const int lane = tid & 31;
    const int row  = blockIdx.x * ROWS_PER_BLK + w;
    const bool valid = row < batch;

    const float* __restrict__ xrow =
        x + (size_t)(valid ? row : batch - 1) * NF;

    // Prefetch tiles 0 and 1 first (independent of g_v -> before the PDL sync).
    #pragma unroll
    for (int s = 0; s < 2; s++) {
        #pragma unroll
        for (int j = 0; j < 4; j++) {
            const int c = (lane + 32 * j) * 4;
            __pipeline_memcpy_async(&sx[s][w][c], xrow + s * TILE + c, 16);
        }
        __pipeline_commit();
    }

    // Wait for build_coef_kernel to fully complete (g_v visible).
    cudaGridDependencySynchronize();

    // Copy v into shared while prefetches are in flight.
    {
        const float4* __restrict__ gv  = (const float4*)g_v;
        float4*       __restrict__ svv = (float4*)sv;
        #pragma unroll
        for (int i = 0; i < (NF / 4) / THREADS; i++)
            svv[tid + i * THREADS] = gv[tid + i * THREADS];
    }
    __syncthreads();

    float acc = 0.0f;

    #pragma unroll
    for (int t = 0; t < NT; t++) {
        if (t < NT - 1) __pipeline_wait_prior(1);
        else            __pipeline_wait_prior(0);

        const float4* __restrict__ xs = (const float4*)sx[t & 1][w];
        const float4* __restrict__ vs = (const float4*)(sv + t * TILE);

        // Pull everything into registers first...
        float4 xa = xs[lane +  0], va = vs[lane +  0];
        float4 xb = xs[lane + 32], vb = vs[lane + 32];
        float4 xc = xs[lane + 64], vc = vs[lane + 64];
        float4 xd = xs[lane + 96], vd = vs[lane + 96];

        // ...then refill the consumed buffer ASAP (thread-local WAR safe)...
        if (t + 2 < NT) {
            #pragma unroll
            for (int j = 0; j < 4; j++) {
                const int c = (lane + 32 * j) * 4;
                __pipeline_memcpy_async(&sx[t & 1][w][c],
                                        xrow + (t + 2) * TILE + c, 16);
            }
            __pipeline_commit();
        }

        // ...then compute.
        float a0 = xa.x * va.x + xa.y * va.y + xa.z * va.z + xa.w * va.w;
        float a1 = xb.x * vb.x + xb.y * vb.y + xb.z * vb.z + xb.w * vb.w;
        float a2 = xc.x * vc.x + xc.y * vc.y + xc.z * vc.z + xc.w * vc.w;
        float a3 = xd.x * vd.x + xd.y * vd.y + xd.z * vd.z + xd.w * vd.w;
        acc += (a0 + a1) + (a2 + a3);
    }

    #pragma unroll
    for (int o = 16; o; o >>= 1) acc += __shfl_xor_sync(0xffffffffu, acc, o);

    if (lane == 0 && valid) out[row] = acc;
}

// Inputs (metadata order): x [B*4096] f32, flat_idx [total], seg_ids [total],
// w_flat [total] f32, diag_w [1024] f32, dense_W [1024] f32. Output: [B] f32.
extern "C" void kernel_launch(void* const* d_in, const int* in_sizes, int n_in,
                              void* d_out, int out_size) {
    const float* x       = (const float*)d_in[0];
    const void*  flatidx = d_in[1];
    const void*  segids  = d_in[2];
    const float* w_flat  = (const float*)d_in[3];
    const float* diag_w  = (const float*)d_in[4];
    const float* dense_W = (const float*)d_in[5];

    int total = in_sizes[1];
    int batch = in_sizes[0] / NF;

    build_coef_kernel<<<1, 1024>>>(flatidx, segids, w_flat, diag_w, dense_W,
                                   total);

    // Launch GEMV with programmatic stream serialization (PDL): it may begin
    // executing (prefetching x) before build_coef_kernel completes; the
    // device-side cudaGridDependencySynchronize() provides the real ordering.
    int blocks = (batch + ROWS_PER_BLK - 1) / ROWS_PER_BLK;
    float* outp = (float*)d_out;

    cudaLaunchConfig_t cfg = {};
    cfg.gridDim  = dim3(blocks, 1, 1);
    cfg.blockDim = dim3(THREADS, 1, 1);
    cfg.dynamicSmemBytes = 0;
    cfg.stream = 0;  // legacy default stream (what the harness captures)

    cudaLaunchAttribute attr;
    attr.id = cudaLaunchAttributeProgrammaticStreamSerialization;
    attr.val.programmaticStreamSerializationAllowed = 1;
    cfg.attrs = &attr;
    cfg.numAttrs = 1;

    cudaLaunchKernelEx(&cfg, gemv_kernel, x, outp, batch);
}